// round 13
// baseline (speedup 1.0000x reference)
#include <cuda_runtime.h>
#include <math.h>

#define B      128
#define P      8732
#define C      21
#define NOBJ   20
#define WT     512
#define S2     2
#define HALF   (P/2)              // 4366
#define HSLOT  ((HALF+WT-1)/WT)   // 9
#define TC     5
#define NC     (NOBJ/TC)          // 4
#define LROWS  384
#define LTILES ((P + LROWS - 1)/LROWS)   // 23
#define WORKERS (S2 + LTILES)     // 25 worker blocks per image
#define GROUP  (WORKERS + 1)      // +1 miner block
#define NALL   (B*GROUP)          // 3328
#define MCH    ((P + WT - 1)/WT)  // 18 priors per miner thread

typedef unsigned long long ull;

__device__ ull           g_bp2[B*S2*NOBJ];  // per-(image,half,truth) best key
__device__ unsigned char g_code[B*P];       // bestn | pos<<7
__device__ float         g_mine[B*P];       // lse - r[0] for every prior
__device__ float         g_ll[B];
__device__ int           g_np[B];
__device__ float         g_lc[B];
__device__ unsigned      g_done[B];         // per-image arrival count (0 at kernel boundaries)
__device__ unsigned      g_ticket;          // never reset: mod-B phase invariant

// ---- dynamic smem layout (miner view; LSE uses first 32256 B as stage) --------
#define HC         8
#define MOFF_V     0                          // P floats
#define MOFF_CODE  (MOFF_V + P*4)             // P bytes
#define MOFF_HIST  ((MOFF_CODE + P + 15) & ~15)   // HC*256 ints
#define MOFF_HC    (MOFF_HIST + HC*256*4)     // 256 ints
#define MOFF_TR    (MOFF_HC + 256*4)          // 100 floats
#define MOFF_P2    (MOFF_TR + 100*4)          // 20 ints
#define MOFF_WS    (MOFF_P2 + 20*4)           // 16 ints
#define MOFF_W1    (MOFF_WS + 16*4)           // 16 floats
#define MOFF_W2    (MOFF_W1 + 16*4)           // 16 floats
#define MOFF_SCAL  (MOFF_W2 + 16*4)           // scalars
#define MSMEM      (MOFF_SCAL + 32)           // ~53.6 KB

__device__ __forceinline__ float sl1(float x) {
    float a = fabsf(x);
    return a < 1.0f ? 0.5f * a * a : a - 0.5f;
}

__global__ __launch_bounds__(WT, 2) void k_all(const float*  __restrict__ conf,
                                               const float4* __restrict__ priors,
                                               const float*  __restrict__ loc,
                                               const float*  __restrict__ targets,
                                               float* __restrict__ out)
{
    extern __shared__ unsigned char msm[];
    float* dsm = (float*)msm;
    int bx = blockIdx.x, tid = threadIdx.x;
    int b = bx / GROUP, rem = bx % GROUP;
    int lane = tid & 31, wid = tid >> 5;

    if (rem < S2) {
        // ================= match role: 2 blocks per image ======================
        ull*    s_bp   = (ull*)dsm;            // 20 ull
        float4* s_tr4  = (float4*)(dsm + 40);  // 20 f4
        float*  s_area = dsm + 120;            // 20 f

        int half = rem;
        int p0 = half * HALF;
        const float* tg = targets + b*NOBJ*5;
        if (tid < NOBJ) {
            float a0 = tg[tid*5+0], a1 = tg[tid*5+1];
            float a2 = tg[tid*5+2], a3 = tg[tid*5+3];
            s_tr4[tid]  = make_float4(a0, a1, a2, a3);
            s_area[tid] = (a2 - a0) * (a3 - a1);
            s_bp[tid]   = 0xFFFFFFFFull;       // floor key: (iou=0, p=0)
        }
        __syncthreads();

        float bestv[HSLOT]; int bestn[HSLOT];
        #pragma unroll
        for (int j = 0; j < HSLOT; j++) { bestv[j] = -1.0f; bestn[j] = 0; }

        for (int c = 0; c < NC; c++) {         // truth chunks of 5 -> low regs
            float    bi[TC], ar5[TC];
            unsigned bp_[TC];
            #pragma unroll
            for (int n = 0; n < TC; n++) {
                bi[n] = 0.0f; bp_[n] = 0xFFFFFFFFu; ar5[n] = s_area[c*TC + n];
            }
            #pragma unroll
            for (int j = 0; j < HSLOT; j++) {
                int i = tid + j*WT;
                if (i < HALF) {
                    int p = p0 + i;
                    float4 pr = __ldg(priors + p);      // L1-hit after chunk 0
                    float hw = pr.z*0.5f, hh = pr.w*0.5f;
                    float bx0 = pr.x-hw, by0 = pr.y-hh;
                    float bx1 = pr.x+hw, by1 = pr.y+hh;
                    float area_b = (bx1-bx0)*(by1-by0);
                    #pragma unroll
                    for (int n5 = 0; n5 < TC; n5++) {
                        int n = c*TC + n5;
                        float4 t = s_tr4[n];
                        float w = fmaxf(fminf(t.z, bx1) - fmaxf(t.x, bx0), 0.0f);
                        float h = fmaxf(fminf(t.w, by1) - fmaxf(t.y, by0), 0.0f);
                        float inter = w * h;
                        if (inter > 0.0f) {             // warp-coherent skip
                            float iou = __fdividef(inter, (ar5[n5] + area_b) - inter);
                            if (iou > bestv[j]) { bestv[j] = iou; bestn[j] = n; }
                            // p ascends in j => strict > keeps earliest p (ties)
                            if (iou > bi[n5]) { bi[n5] = iou; bp_[n5] = (unsigned)p; }
                        }
                    }
                }
            }
            #pragma unroll
            for (int n5 = 0; n5 < TC; n5++) {           // key built ONCE per chunk
                ull k = ((ull)__float_as_uint(bi[n5]) << 32) | (ull)(~bp_[n5]);
                #pragma unroll
                for (int o = 16; o > 0; o >>= 1) {
                    ull x = __shfl_down_sync(0xffffffffu, k, o);
                    if (x > k) k = x;
                }
                if (lane == 0) atomicMax(&s_bp[c*TC + n5], k);
            }
        }
        #pragma unroll
        for (int j = 0; j < HSLOT; j++) {
            int i = tid + j*WT;
            if (i < HALF)
                g_code[b*P + p0 + i] =
                    (unsigned char)(bestn[j] | ((bestv[j] < 0.5f) ? 0 : 0x80));
        }
        __syncthreads();
        if (tid < NOBJ) g_bp2[(b*S2 + half)*NOBJ + tid] = s_bp[tid];
        // signal arrival
        __threadfence();
        __syncthreads();
        if (tid == 0) atomicAdd(&g_done[b], 1u);
    } else if (rem < WORKERS) {
        // ================= lse role: 23 blocks per image =======================
        float* s_stage = dsm;                  // LROWS*C floats = 32256 B
        int tile = rem - S2;
        int t0 = tile * LROWS, rows = min(LROWS, P - t0);
        int elems = rows * C;
        size_t base_f = ((size_t)b*P + t0) * C;
        size_t a0 = (base_f + 3) & ~(size_t)3;         // first 16B-aligned float
        int head = (int)(a0 - base_f);                  // 0..3
        if (tid < head) s_stage[tid] = __ldg(conf + base_f + tid);
        int rest = elems - head;
        int nq = rest >> 2;
        const float4* cq = (const float4*)conf + (a0 >> 2);
        for (int q = tid; q < nq; q += WT) {
            float4 v = __ldg(cq + q);
            int s = head + q*4;
            s_stage[s+0] = v.x; s_stage[s+1] = v.y;
            s_stage[s+2] = v.z; s_stage[s+3] = v.w;
        }
        int tstart = head + nq*4;
        if (tid < elems - tstart)                       // 0..3 tail scalars
            s_stage[tstart + tid] = __ldg(conf + base_f + tstart + tid);
        __syncthreads();
        if (tid < rows) {
            const float* r = s_stage + tid * C;         // stride 21: conflict-free
            float mx = r[0];
            #pragma unroll
            for (int c2 = 1; c2 < C; c2++) mx = fmaxf(mx, r[c2]);
            float s = 0.0f;
            #pragma unroll
            for (int c2 = 0; c2 < C; c2++) s += __expf(r[c2] - mx);
            float lse = mx + __logf(s);
            g_mine[(size_t)b*P + t0 + tid] = lse - r[0];
        }
        __threadfence();
        __syncthreads();
        if (tid == 0) atomicAdd(&g_done[b], 1u);
    } else {
        // ================= miner role: 1 block per image =======================
        float*         s_v    = (float*)(msm + MOFF_V);
        unsigned char* s_code = msm + MOFF_CODE;
        int*           hist   = (int*)  (msm + MOFF_HIST);
        int*           histC  = (int*)  (msm + MOFF_HC);
        float*         s_tr   = (float*)(msm + MOFF_TR);
        int*           s_p2   = (int*)  (msm + MOFF_P2);
        int*           s_ws   = (int*)  (msm + MOFF_WS);
        float*         s_w1   = (float*)(msm + MOFF_W1);
        float*         s_w2   = (float*)(msm + MOFF_W2);
        unsigned*      s_pref = (unsigned*)(msm + MOFF_SCAL);
        int*           s_klft = (int*)  (msm + MOFF_SCAL + 4);
        float*         s_ce0  = (float*)(msm + MOFF_SCAL + 8);
        int*           s_last = (int*)  (msm + MOFF_SCAL + 12);

        // spin until this image's 25 workers are done
        if (tid == 0) {
            while (atomicAdd(&g_done[b], 0u) < (unsigned)WORKERS) { }
            __threadfence();
        }
        __syncthreads();

        // stage mine values + code bytes (coalesced), truths, best-prior idx
        const float4* gm4 = (const float4*)(g_mine + (size_t)b*P);
        float4* sv4 = (float4*)s_v;
        for (int i = tid; i < P/4; i += WT) sv4[i] = gm4[i];
        const unsigned* gc = (const unsigned*)(g_code + b*P);
        unsigned* sc = (unsigned*)s_code;
        for (int i = tid; i < P/4; i += WT) sc[i] = gc[i];
        if (tid < NOBJ*5) s_tr[tid] = targets[b*NOBJ*5 + tid];
        if (tid < NOBJ) {
            ull k = 0ull;
            #pragma unroll
            for (int o = 0; o < S2; o++) {
                ull x = g_bp2[(b*S2 + o)*NOBJ + tid];
                if (x > k) k = x;
            }
            s_p2[tid] = (int)(0xFFFFFFFFu - (unsigned)(k & 0xFFFFFFFFull));
        }
        __syncthreads();
        if (tid == 0) {   // ascending m, last write wins = JAX "chosen = max n"
            for (int m = 0; m < NOBJ; m++) s_code[s_p2[m]] = (unsigned char)(m | 0x80);
        }
        __syncthreads();

        // ---- fixup + key build (keys in registers, contiguous ownership) -----
        int lo = tid * MCH, hi = min(lo + MCH, P);
        unsigned keys[MCH];
        float ll = 0.0f, ce_pos = 0.0f; int np = 0;
        #pragma unroll
        for (int j = 0; j < MCH; j++) {
            int p = lo + j;
            unsigned key = 0u;
            if (p < P) {
                unsigned char code = s_code[p];
                float v = s_v[p];
                if (code & 0x80) {
                    int n = code & 31;
                    np++;
                    size_t idx = (size_t)b*P + p;
                    int cf = (int)s_tr[n*5+4] + 1;
                    float r0  = __ldg(conf + idx*C);
                    float rcf = __ldg(conf + idx*C + cf);
                    ce_pos += v + r0 - rcf;             // (lse-r0)+r0-rcf
                    float4 pr = __ldg(priors + p);
                    float a0 = s_tr[n*5+0], a1 = s_tr[n*5+1];
                    float a2 = s_tr[n*5+2], a3 = s_tr[n*5+3];
                    float gx = ((a0 + a2) * 0.5f - pr.x) / (0.1f * pr.z);
                    float gy = ((a1 + a3) * 0.5f - pr.y) / (0.1f * pr.w);
                    float gw = logf((a2 - a0) / pr.z) * 5.0f;
                    float gh = logf((a3 - a1) / pr.w) * 5.0f;
                    float4 ld = __ldg(((const float4*)loc) + idx);
                    ll += sl1(ld.x - gx) + sl1(ld.y - gy)
                        + sl1(ld.z - gw) + sl1(ld.w - gh);
                    // key stays 0: positives excluded (all selected keys > 0)
                } else {
                    if (b == 0 && p == 0) {
                        // clamped[0]=1 quirk: recompute lse, IDENTICAL op sequence
                        float rr[C];
                        #pragma unroll
                        for (int c2 = 0; c2 < C; c2++) rr[c2] = __ldg(conf + c2);
                        float mx = rr[0];
                        #pragma unroll
                        for (int c2 = 1; c2 < C; c2++) mx = fmaxf(mx, rr[c2]);
                        float s = 0.0f;
                        #pragma unroll
                        for (int c2 = 0; c2 < C; c2++) s += __expf(rr[c2] - mx);
                        float lse = mx + __logf(s);
                        *s_ce0 = lse - rr[0];           // true CE if selected
                        v = lse - rr[1];                // mining value uses class 1
                    }
                    key = (v < 0.0f) ? 0u : __float_as_uint(v);
                }
            }
            keys[j] = key;
        }
        // np reduce (warp shuffle + 16-slot stage)
        #pragma unroll
        for (int o = 16; o > 0; o >>= 1) np += __shfl_down_sync(0xffffffffu, np, o);
        if (lane == 0) s_ws[wid] = np;
        __syncthreads();
        if (wid == 0) {
            int v2 = (lane < WT/32) ? s_ws[lane] : 0;
            #pragma unroll
            for (int o = 8; o > 0; o >>= 1) v2 += __shfl_down_sync(0xffffffffu, v2, o);
            if (lane == 0) *s_klft = v2;                // stash np_tot
        }
        __syncthreads();
        int np_tot = *s_klft;
        __syncthreads();

        // ---- exact top-k radix select on register keys -----------------------
        int k = 3 * np_tot; if (k > P - 1) k = P - 1;
        int negc = P - np_tot;
        float nsum = 0.0f;
        bool q0neg = ((s_code[0] & 0x80) == 0);         // (0,0) is a negative
        int* myhist = hist + (wid & (HC-1)) * 256;

        if (k >= negc) {
            #pragma unroll
            for (int j = 0; j < MCH; j++) nsum += __uint_as_float(keys[j]);
            if (b == 0 && tid == 0 && q0neg)
                nsum += *s_ce0 - __uint_as_float(keys[0]);
        } else {
            unsigned pref = 0; int kleft = k;
            for (int shift = 24; shift >= 0; shift -= 8) {
                for (int i = tid; i < HC*256; i += WT) hist[i] = 0;
                __syncthreads();
                #pragma unroll
                for (int j = 0; j < MCH; j++) {
                    unsigned kh = keys[j] >> shift;
                    bool ok = (shift == 24) || ((kh >> 8) == pref);
                    if (ok) atomicAdd(&myhist[kh & 255u], 1);
                }
                __syncthreads();
                if (tid < 256) {
                    int s = 0;
                    #pragma unroll
                    for (int c2 = 0; c2 < HC; c2++) s += hist[c2*256 + tid];
                    histC[tid] = s;
                }
                __syncthreads();
                if (wid == 0) {                          // warp-only bin select
                    int c[8]; int tot = 0;
                    #pragma unroll
                    for (int j = 0; j < 8; j++) { c[j] = histC[lane*8 + j]; tot += c[j]; }
                    int suf = tot;
                    #pragma unroll
                    for (int o = 1; o < 32; o <<= 1) {
                        int y = __shfl_down_sync(0xffffffffu, suf, o);
                        if (lane + o < 32) suf += y;
                    }
                    int cum = suf - tot;
                    #pragma unroll
                    for (int j = 7; j >= 0; j--) {
                        if (cum < kleft && cum + c[j] >= kleft) {
                            *s_pref = (pref << 8) | (unsigned)(lane*8 + j);
                            *s_klft = kleft - cum;
                        }
                        cum += c[j];
                    }
                }
                __syncthreads();
                pref = *s_pref; kleft = *s_klft;
            }
            unsigned T = pref; int quota = kleft;        // quota >= 1

            int ct = 0;
            #pragma unroll
            for (int j = 0; j < MCH; j++) {
                unsigned key = keys[j];
                if (key > T) nsum += __uint_as_float(key);
                else if (key == T) ct++;
            }
            int cin = ct;
            #pragma unroll
            for (int o = 1; o < 32; o <<= 1) {
                int n2 = __shfl_up_sync(0xffffffffu, cin, o);
                if (lane >= o) cin += n2;
            }
            if (lane == 31) s_ws[wid] = cin;
            __syncthreads();
            if (wid == 0) {
                int w = (lane < WT/32) ? s_ws[lane] : 0;
                #pragma unroll
                for (int o = 1; o < 32; o <<= 1) {
                    int n2 = __shfl_up_sync(0xffffffffu, w, o);
                    if (lane >= o) w += n2;
                }
                if (lane < WT/32) s_ws[lane] = w;
            }
            __syncthreads();
            int off0 = ((wid == 0) ? 0 : s_ws[wid - 1]) + (cin - ct);
            int r2 = 0;
            #pragma unroll
            for (int j = 0; j < MCH; j++) {              // ties stable by index
                if (keys[j] == T) {
                    if (off0 + r2 < quota) nsum += __uint_as_float(keys[j]);
                    r2++;
                }
            }
            // note: if T==0, positives tie in as zeros (add 0.0) — harmless
            if (b == 0 && tid == 0 && q0neg && keys[0] >= T)
                nsum += *s_ce0 - __uint_as_float(keys[0]);
        }

        // ---- ll & lc reduce, per-image partials, ticketed final --------------
        float lc = ce_pos + nsum;
        #pragma unroll
        for (int o = 16; o > 0; o >>= 1) {
            lc += __shfl_down_sync(0xffffffffu, lc, o);
            ll += __shfl_down_sync(0xffffffffu, ll, o);
        }
        if (lane == 0) { s_w1[wid] = lc; s_w2[wid] = ll; }
        __syncthreads();
        if (wid == 0) {
            float a = (lane < WT/32) ? s_w1[lane] : 0.0f;
            float d = (lane < WT/32) ? s_w2[lane] : 0.0f;
            #pragma unroll
            for (int o = 8; o > 0; o >>= 1) {
                a += __shfl_down_sync(0xffffffffu, a, o);
                d += __shfl_down_sync(0xffffffffu, d, o);
            }
            if (lane == 0) {
                g_ll[b] = d; g_lc[b] = a; g_np[b] = np_tot;
                __threadfence();
                unsigned t = atomicAdd(&g_ticket, 1u);
                *s_last = ((t % B) == B - 1);            // phase-correct, no reset
            }
        }
        __syncthreads();

        if (*s_last) {                                   // last miner: final reduce
            __threadfence();
            float* fA = s_v; float* fB = s_v + 256; int* iC = hist;
            float llg = 0.0f, lcg = 0.0f; int npg = 0;
            if (tid < B) { llg = g_ll[tid]; lcg = g_lc[tid]; npg = g_np[tid]; }
            if (tid < 256) { fA[tid] = llg; fB[tid] = lcg; iC[tid] = npg; }
            __syncthreads();
            for (int o = 64; o > 0; o >>= 1) {
                if (tid < o) { fA[tid] += fA[tid+o]; fB[tid] += fB[tid+o]; iC[tid] += iC[tid+o]; }
                __syncthreads();
            }
            if (tid == 0) {
                float Nf = (float)iC[0];
                out[0] = fA[0] / Nf;
                out[1] = fB[0] / Nf;
            }
        }
        __syncthreads();
        if (tid == 0) atomicSub(&g_done[b], (unsigned)WORKERS);  // restore 0
    }
}

// ------------- launch ------------------------------------------------------------
extern "C" void kernel_launch(void* const* d_in, const int* in_sizes, int n_in,
                              void* d_out, int out_size)
{
    const float *loc = nullptr, *conf = nullptr, *priors = nullptr, *targets = nullptr;
    for (int i = 0; i < n_in; i++) {
        long long sz = in_sizes[i];
        if      (sz == (long long)B*P*4)     loc     = (const float*)d_in[i];
        else if (sz == (long long)B*P*C)     conf    = (const float*)d_in[i];
        else if (sz == (long long)P*4)       priors  = (const float*)d_in[i];
        else if (sz == (long long)B*NOBJ*5)  targets = (const float*)d_in[i];
    }
    static int attr_done = 0;
    if (!attr_done) {
        cudaFuncSetAttribute(k_all, cudaFuncAttributeMaxDynamicSharedMemorySize, MSMEM);
        attr_done = 1;
    }
    k_all<<<NALL, WT, MSMEM>>>(conf, (const float4*)priors, loc, targets, (float*)d_out);
    (void)out_size;
}

// round 14
// speedup vs baseline: 1.3055x; 1.3055x over previous
#include <cuda_runtime.h>
#include <math.h>

#define B      128
#define P      8732
#define C      21
#define NOBJ   20
#define WT     512
#define S2     2
#define HALF   (P/2)              // 4366
#define HSLOT  ((HALF+WT-1)/WT)   // 9
#define TC     5
#define NC     (NOBJ/TC)          // 4
#define LROWS  384
#define LTILES ((P + LROWS - 1)/LROWS)   // 23
#define GROUP  (S2 + LTILES)      // 25 blocks per image
#define NWORK  (B*GROUP)          // 3200
#define LBYTES (LROWS*C*4)        // 32256 B dynamic smem
#define MT     1024
#define MK     ((P + MT - 1)/MT)  // 9 keys per minefix thread
#define HC     8                  // histogram copies

typedef unsigned long long ull;

__device__ ull           g_bp2[B*S2*NOBJ];  // per-(image,half,truth) best key
__device__ unsigned char g_code[B*P];       // bestn | pos<<7
__device__ float         g_mine[B*P];       // lse - r[0] for every prior
__device__ float         g_ll[B];
__device__ int           g_np[B];
__device__ float         g_lc[B];
__device__ unsigned      g_ticket;          // never reset: mod-B phase invariant

__device__ __forceinline__ float sl1(float x) {
    float a = fabsf(x);
    return a < 1.0f ? 0.5f * a * a : a - 0.5f;
}

// ------------- kernel 1: fused match (compute) + lse (DRAM) roles --------------
__global__ __launch_bounds__(WT) void k_work(const float*  __restrict__ conf,
                                             const float4* __restrict__ priors,
                                             const float*  __restrict__ targets)
{
    extern __shared__ float dsm[];
    int bx = blockIdx.x, tid = threadIdx.x;
    int b = bx / GROUP, rem = bx % GROUP;
    int lane = tid & 31;

    if (rem < S2) {
        // ========== match role: 2 blocks per image, DIVISION-FREE hot loop =====
        ull*    s_bp   = (ull*)dsm;            // 20 ull
        float4* s_tr4  = (float4*)(dsm + 40);  // 20 f4
        float*  s_area = dsm + 120;            // 20 f

        int half = rem;
        int p0 = half * HALF;
        const float* tg = targets + b*NOBJ*5;
        if (tid < NOBJ) {
            float a0 = tg[tid*5+0], a1 = tg[tid*5+1];
            float a2 = tg[tid*5+2], a3 = tg[tid*5+3];
            s_tr4[tid]  = make_float4(a0, a1, a2, a3);
            s_area[tid] = (a2 - a0) * (a3 - a1);
            s_bp[tid]   = 0xFFFFFFFFull;       // floor key: (iou=0, p=0)
        }
        __syncthreads();

        // per-prior best over truths as (inter, uni) pair: argmax w/o division
        float bI[HSLOT], bU[HSLOT]; int bN[HSLOT];
        #pragma unroll
        for (int j = 0; j < HSLOT; j++) { bI[j] = 0.0f; bU[j] = 1.0f; bN[j] = 0; }

        for (int c = 0; c < NC; c++) {         // truth chunks of 5 -> low regs
            float    ti[TC], tu[TC], ar5[TC];
            unsigned tp[TC];
            #pragma unroll
            for (int n = 0; n < TC; n++) {
                ti[n] = 0.0f; tu[n] = 1.0f; tp[n] = 0xFFFFFFFFu;
                ar5[n] = s_area[c*TC + n];
            }
            #pragma unroll
            for (int j = 0; j < HSLOT; j++) {
                int i = tid + j*WT;
                if (i < HALF) {
                    int p = p0 + i;
                    float4 pr = __ldg(priors + p);      // L1-hit after chunk 0
                    float hw = pr.z*0.5f, hh = pr.w*0.5f;
                    float bx0 = pr.x-hw, by0 = pr.y-hh;
                    float bx1 = pr.x+hw, by1 = pr.y+hh;
                    float area_b = (bx1-bx0)*(by1-by0);
                    #pragma unroll
                    for (int n5 = 0; n5 < TC; n5++) {
                        int n = c*TC + n5;
                        float4 t = s_tr4[n];
                        float w = fmaxf(fminf(t.z, bx1) - fmaxf(t.x, bx0), 0.0f);
                        float h = fmaxf(fminf(t.w, by1) - fmaxf(t.y, by0), 0.0f);
                        float inter = w * h;
                        if (inter > 0.0f) {             // warp-coherent skip
                            float uni = (ar5[n5] + area_b) - inter;
                            // argmax over n: inter/uni > bI/bU  (exact, no div)
                            if (inter * bU[j] > bI[j] * uni) {
                                bI[j] = inter; bU[j] = uni; bN[j] = n;
                            }
                            // best prior for this truth (p ascends in j: ties->earliest)
                            if (inter * tu[n5] > ti[n5] * uni) {
                                ti[n5] = inter; tu[n5] = uni; tp[n5] = (unsigned)p;
                            }
                        }
                    }
                }
            }
            #pragma unroll
            for (int n5 = 0; n5 < TC; n5++) {           // warp reduce (inter,uni,p)
                float    vi = ti[n5], vu = tu[n5];
                unsigned vp = tp[n5];
                #pragma unroll
                for (int o = 16; o > 0; o >>= 1) {
                    float    xi = __shfl_down_sync(0xffffffffu, vi, o);
                    float    xu = __shfl_down_sync(0xffffffffu, vu, o);
                    unsigned xp = __shfl_down_sync(0xffffffffu, vp, o);
                    float l = xi * vu, r = vi * xu;
                    if (l > r || (l == r && xp < vp)) { vi = xi; vu = xu; vp = xp; }
                }
                if (lane == 0) {
                    float iou = vi / vu;                // div.rn: matches JAX rounding
                    ull key = ((ull)__float_as_uint(iou) << 32) | (ull)(~vp);
                    atomicMax(&s_bp[c*TC + n5], key);
                }
            }
        }
        #pragma unroll
        for (int j = 0; j < HSLOT; j++) {
            int i = tid + j*WT;
            if (i < HALF) {
                bool pos = (2.0f * bI[j] >= bU[j]);     // iou >= 0.5, division-free
                g_code[b*P + p0 + i] = (unsigned char)(bN[j] | (pos ? 0x80 : 0));
            }
        }
        __syncthreads();
        if (tid < NOBJ) g_bp2[(b*S2 + half)*NOBJ + tid] = s_bp[tid];
    } else {
        // ========== lse role: 23 blocks per image, float4 streaming ============
        float* s_stage = dsm;                  // LROWS*C floats = 32256 B
        int tile = rem - S2;
        int t0 = tile * LROWS, rows = min(LROWS, P - t0);
        int elems = rows * C;
        size_t base_f = ((size_t)b*P + t0) * C;
        size_t a0 = (base_f + 3) & ~(size_t)3;         // first 16B-aligned float
        int head = (int)(a0 - base_f);                  // 0..3
        if (tid < head) s_stage[tid] = __ldg(conf + base_f + tid);
        int rest = elems - head;
        int nq = rest >> 2;
        const float4* cq = (const float4*)conf + (a0 >> 2);
        for (int q = tid; q < nq; q += WT) {
            float4 v = __ldg(cq + q);
            int s = head + q*4;
            s_stage[s+0] = v.x; s_stage[s+1] = v.y;
            s_stage[s+2] = v.z; s_stage[s+3] = v.w;
        }
        int tstart = head + nq*4;
        if (tid < elems - tstart)                       // 0..3 tail scalars
            s_stage[tstart + tid] = __ldg(conf + base_f + tstart + tid);
        __syncthreads();
        if (tid < rows) {
            const float* r = s_stage + tid * C;         // stride 21: conflict-free
            float mx = r[0];
            #pragma unroll
            for (int c2 = 1; c2 < C; c2++) mx = fmaxf(mx, r[c2]);
            float s = 0.0f;
            #pragma unroll
            for (int c2 = 0; c2 < C; c2++) s += __expf(r[c2] - mx);
            float lse = mx + __logf(s);
            g_mine[(size_t)b*P + t0 + tid] = lse - r[0];
        }
    }
}

// ------------- kernel 2: fixup + mining (register keys) + final ----------------
__global__ __launch_bounds__(MT) void k_minefix(const float*  __restrict__ conf,
                                                const float4* __restrict__ priors,
                                                const float*  __restrict__ loc,
                                                const float*  __restrict__ targets,
                                                float* __restrict__ out)
{
    __shared__ unsigned char s_code[P];
    __shared__ int   hist[HC*256];
    __shared__ int   histC[256];
    __shared__ float s_tr[NOBJ*5];
    __shared__ int   s_p2[NOBJ];
    __shared__ int   s_ws[32];
    __shared__ float s_w1[32], s_w2[32];
    __shared__ unsigned s_pref;
    __shared__ int   s_klft, s_last, s_npt;
    __shared__ float s_ce0;

    int b = blockIdx.x, tid = threadIdx.x;
    int lane = tid & 31, wid = tid >> 5;

    const unsigned* gc = (const unsigned*)(g_code + b*P);  // P % 4 == 0
    unsigned* sc = (unsigned*)s_code;
    for (int i = tid; i < P/4; i += MT) sc[i] = gc[i];
    if (tid < NOBJ*5) s_tr[tid] = targets[b*NOBJ*5 + tid];
    if (tid < NOBJ) {
        ull k = 0ull;                          // reduce 2 per-half slots
        #pragma unroll
        for (int o = 0; o < S2; o++) {
            ull x = g_bp2[(b*S2 + o)*NOBJ + tid];
            if (x > k) k = x;
        }
        s_p2[tid] = (int)(0xFFFFFFFFu - (unsigned)(k & 0xFFFFFFFFull));
    }
    __syncthreads();
    if (tid == 0) {   // ascending m, last write wins = JAX "chosen = max n"
        for (int m = 0; m < NOBJ; m++) s_code[s_p2[m]] = (unsigned char)(m | 0x80);
    }
    __syncthreads();

    // ---- fixup + key build: keys resident in registers (contiguous chunks) ----
    int lo = tid * MK;
    unsigned keys[MK];
    float ll = 0.0f, ce_pos = 0.0f; int np = 0;
    #pragma unroll
    for (int j = 0; j < MK; j++) {
        int p = lo + j;
        unsigned key = 0u;                      // padding & positives: excluded
        if (p < P) {
            unsigned char code = s_code[p];
            float v = g_mine[(size_t)b*P + p];  // warp touches 9 L1 lines, reused
            if (code & 0x80) {
                int n = code & 31;
                np++;
                size_t idx = (size_t)b*P + p;
                int cf = (int)s_tr[n*5+4] + 1;
                float r0  = __ldg(conf + idx*C);
                float rcf = __ldg(conf + idx*C + cf);
                ce_pos += v + r0 - rcf;         // (lse-r0)+r0-rcf
                float4 pr = __ldg(priors + p);
                float a0 = s_tr[n*5+0], a1 = s_tr[n*5+1];
                float a2 = s_tr[n*5+2], a3 = s_tr[n*5+3];
                float gx = ((a0 + a2) * 0.5f - pr.x) / (0.1f * pr.z);
                float gy = ((a1 + a3) * 0.5f - pr.y) / (0.1f * pr.w);
                float gw = logf((a2 - a0) / pr.z) * 5.0f;
                float gh = logf((a3 - a1) / pr.w) * 5.0f;
                float4 ld = __ldg(((const float4*)loc) + idx);
                ll += sl1(ld.x - gx) + sl1(ld.y - gy)
                    + sl1(ld.z - gw) + sl1(ld.w - gh);
            } else {
                if (b == 0 && p == 0) {
                    // clamped[0]=1 quirk: recompute lse, IDENTICAL op sequence
                    float rr[C];
                    #pragma unroll
                    for (int c2 = 0; c2 < C; c2++) rr[c2] = __ldg(conf + c2);
                    float mx = rr[0];
                    #pragma unroll
                    for (int c2 = 1; c2 < C; c2++) mx = fmaxf(mx, rr[c2]);
                    float s = 0.0f;
                    #pragma unroll
                    for (int c2 = 0; c2 < C; c2++) s += __expf(rr[c2] - mx);
                    float lse = mx + __logf(s);
                    s_ce0 = lse - rr[0];        // true CE if selected
                    v = lse - rr[1];            // mining value uses class 1
                }
                key = (v < 0.0f) ? 0u : __float_as_uint(v);
            }
        }
        keys[j] = key;
    }
    // np reduce (warp shuffle + 32-slot stage)
    #pragma unroll
    for (int o = 16; o > 0; o >>= 1) np += __shfl_down_sync(0xffffffffu, np, o);
    if (lane == 0) s_ws[wid] = np;
    __syncthreads();
    if (wid == 0) {
        int v2 = s_ws[lane];
        #pragma unroll
        for (int o = 16; o > 0; o >>= 1) v2 += __shfl_down_sync(0xffffffffu, v2, o);
        if (lane == 0) s_npt = v2;
    }
    __syncthreads();
    int np_tot = s_npt;

    // ---- exact top-k radix select on register keys ----------------------------
    int k = 3 * np_tot; if (k > P - 1) k = P - 1;
    int negc = P - np_tot;
    float nsum = 0.0f;
    bool q0neg = ((s_code[0] & 0x80) == 0);
    int* myhist = hist + (wid & (HC-1)) * 256;

    if (k >= negc) {
        #pragma unroll
        for (int j = 0; j < MK; j++) nsum += __uint_as_float(keys[j]);
        if (b == 0 && tid == 0 && q0neg)
            nsum += s_ce0 - __uint_as_float(keys[0]);
    } else {
        unsigned pref = 0; int kleft = k;
        for (int shift = 24; shift >= 0; shift -= 8) {
            for (int i = tid; i < HC*256; i += MT) hist[i] = 0;
            __syncthreads();
            #pragma unroll
            for (int j = 0; j < MK; j++) {
                unsigned kh = keys[j] >> shift;
                bool ok = (shift == 24) || ((kh >> 8) == pref);
                if (ok) atomicAdd(&myhist[kh & 255u], 1);
            }
            __syncthreads();
            if (tid < 256) {
                int s = 0;
                #pragma unroll
                for (int c2 = 0; c2 < HC; c2++) s += hist[c2*256 + tid];
                histC[tid] = s;
            }
            __syncthreads();
            if (wid == 0) {                     // warp-only bin select
                int c[8]; int tot = 0;
                #pragma unroll
                for (int j = 0; j < 8; j++) { c[j] = histC[lane*8 + j]; tot += c[j]; }
                int suf = tot;
                #pragma unroll
                for (int o = 1; o < 32; o <<= 1) {
                    int y = __shfl_down_sync(0xffffffffu, suf, o);
                    if (lane + o < 32) suf += y;
                }
                int cum = suf - tot;
                #pragma unroll
                for (int j = 7; j >= 0; j--) {
                    if (cum < kleft && cum + c[j] >= kleft) {
                        s_pref = (pref << 8) | (unsigned)(lane*8 + j);
                        s_klft = kleft - cum;
                    }
                    cum += c[j];
                }
            }
            __syncthreads();
            pref = s_pref; kleft = s_klft;
            __syncthreads();
        }
        unsigned T = pref; int quota = kleft;   // quota >= 1, T > 0

        int ct = 0;
        #pragma unroll
        for (int j = 0; j < MK; j++) {
            unsigned key = keys[j];
            if (key > T) nsum += __uint_as_float(key);
            else if (key == T) ct++;
        }
        int cin = ct;
        #pragma unroll
        for (int o = 1; o < 32; o <<= 1) {
            int n2 = __shfl_up_sync(0xffffffffu, cin, o);
            if (lane >= o) cin += n2;
        }
        if (lane == 31) s_ws[wid] = cin;
        __syncthreads();
        if (wid == 0) {
            int w = s_ws[lane];
            #pragma unroll
            for (int o = 1; o < 32; o <<= 1) {
                int n2 = __shfl_up_sync(0xffffffffu, w, o);
                if (lane >= o) w += n2;
            }
            s_ws[lane] = w;
        }
        __syncthreads();
        int off0 = ((wid == 0) ? 0 : s_ws[wid - 1]) + (cin - ct);
        int r2 = 0;
        #pragma unroll
        for (int j = 0; j < MK; j++) {          // ties stable by ascending index
            if (keys[j] == T) {
                if (off0 + r2 < quota) nsum += __uint_as_float(keys[j]);
                r2++;
            }
        }
        if (b == 0 && tid == 0 && q0neg && keys[0] >= T)
            nsum += s_ce0 - __uint_as_float(keys[0]);
    }

    // ---- ll & lc reduce: warp shuffle + 32-slot stages ------------------------
    float lc = ce_pos + nsum;
    #pragma unroll
    for (int o = 16; o > 0; o >>= 1) {
        lc += __shfl_down_sync(0xffffffffu, lc, o);
        ll += __shfl_down_sync(0xffffffffu, ll, o);
    }
    if (lane == 0) { s_w1[wid] = lc; s_w2[wid] = ll; }
    __syncthreads();
    if (wid == 0) {
        float a = s_w1[lane], d = s_w2[lane];
        #pragma unroll
        for (int o = 16; o > 0; o >>= 1) {
            a += __shfl_down_sync(0xffffffffu, a, o);
            d += __shfl_down_sync(0xffffffffu, d, o);
        }
        if (lane == 0) {
            g_ll[b] = d; g_lc[b] = a; g_np[b] = np_tot;
            __threadfence();
            unsigned t = atomicAdd(&g_ticket, 1u);
            s_last = ((t % B) == B - 1);        // phase-correct, no reset needed
        }
    }
    __syncthreads();

    if (s_last) {                               // last block: final reduce
        __threadfence();
        float* fA = (float*)hist;               // hist is free now
        float* fB = fA + 128;
        int*   iC = (int*)(fB + 128);
        float llg = 0.0f, lcg = 0.0f; int npg = 0;
        if (tid < B) { llg = g_ll[tid]; lcg = g_lc[tid]; npg = g_np[tid]; }
        if (tid < 128) { fA[tid] = llg; fB[tid] = lcg; iC[tid] = npg; }
        __syncthreads();
        for (int o = 64; o > 0; o >>= 1) {
            if (tid < o) { fA[tid] += fA[tid+o]; fB[tid] += fB[tid+o]; iC[tid] += iC[tid+o]; }
            __syncthreads();
        }
        if (tid == 0) {
            float Nf = (float)iC[0];
            out[0] = fA[0] / Nf;
            out[1] = fB[0] / Nf;
        }
    }
}

// ------------- launch ------------------------------------------------------------
extern "C" void kernel_launch(void* const* d_in, const int* in_sizes, int n_in,
                              void* d_out, int out_size)
{
    const float *loc = nullptr, *conf = nullptr, *priors = nullptr, *targets = nullptr;
    for (int i = 0; i < n_in; i++) {
        long long sz = in_sizes[i];
        if      (sz == (long long)B*P*4)     loc     = (const float*)d_in[i];
        else if (sz == (long long)B*P*C)     conf    = (const float*)d_in[i];
        else if (sz == (long long)P*4)       priors  = (const float*)d_in[i];
        else if (sz == (long long)B*NOBJ*5)  targets = (const float*)d_in[i];
    }
    k_work   <<<NWORK, WT, LBYTES>>>(conf, (const float4*)priors, targets);
    k_minefix<<<B, MT>>>(conf, (const float4*)priors, loc, targets, (float*)d_out);
    (void)out_size;
}